// round 2
// baseline (speedup 1.0000x reference)
#include <cuda_runtime.h>

#define T_DIM 512
#define B_DIM 256
#define N_DIM 128
#define BN    (B_DIM * N_DIM)

// Scratch (no device allocation allowed)
__device__ float g_score[B_DIM];
__device__ float g_logZ[B_DIM];
__device__ int   g_len[B_DIM];

// ---------------------------------------------------------------------------
// Kernel A: per-b gold-path score + sequence length (mask is prefix-true).
// One warp per batch element. mask arrives as int32 (harness upcasts bool).
// ---------------------------------------------------------------------------
__global__ void score_len_kernel(const float* __restrict__ emit,
                                 const int*   __restrict__ target,
                                 const int*   __restrict__ mask,
                                 const float* __restrict__ trans,
                                 const float* __restrict__ strans,
                                 const float* __restrict__ etrans) {
    int warp = (blockIdx.x * blockDim.x + threadIdx.x) >> 5;
    int lane = threadIdx.x & 31;
    if (warp >= B_DIM) return;
    const int b = warp;

    float s = 0.f;
    int cnt = 0;
    for (int t = lane; t < T_DIM; t += 32) {
        if (mask[t * B_DIM + b] != 0) {
            int tg = target[t * B_DIM + b];
            float v = emit[t * BN + b * N_DIM + tg];
            if (t > 0) {
                int tp = target[(t - 1) * B_DIM + b];
                v += trans[tp * N_DIM + tg];
            }
            s += v;
            cnt += 1;
        }
    }
    #pragma unroll
    for (int o = 16; o; o >>= 1) {
        s   += __shfl_xor_sync(0xffffffffu, s, o);
        cnt += __shfl_xor_sync(0xffffffffu, cnt, o);
    }
    if (lane == 0) {
        s += strans[target[b]];                          // target[0, b]
        s += etrans[target[(cnt - 1) * B_DIM + b]];      // target[len-1, b]
        g_score[b] = s;
        g_len[b]   = cnt;
    }
}

// ---------------------------------------------------------------------------
// Kernel B: forward algorithm. One CTA per batch element.
// 256 threads: j = tid & 127 (output tag), h = tid >> 7 (K-split half).
// E = exp(trans) held in registers (64 per thread), p = exp(alpha - m) in smem.
// ---------------------------------------------------------------------------
__global__ void __launch_bounds__(256, 2)
forward_kernel(const float* __restrict__ emit,
               const float* __restrict__ trans,
               const float* __restrict__ strans,
               const float* __restrict__ etrans) {
    __shared__ float p[N_DIM];      // exp-shifted alpha
    __shared__ float psum[N_DIM];   // partial from half h=1
    __shared__ float wred[8];       // per-warp reduction slots

    const int b    = blockIdx.x;
    const int tid  = threadIdx.x;
    const int j    = tid & (N_DIM - 1);
    const int h    = tid >> 7;        // 0 or 1
    const int lane = tid & 31;
    const int wid  = tid >> 5;        // 0..7

    // Load E column j, rows [h*64, h*64+64) into registers.
    float E[64];
    #pragma unroll
    for (int k = 0; k < 64; k++)
        E[k] = __expf(trans[(h * 64 + k) * N_DIM + j]);

    const int len = g_len[b];

    // ---- init: alpha0 = strans + emit[0] ----
    float a = 0.f, e_cur = 0.f, m;
    if (h == 0) {
        a = strans[j] + emit[b * N_DIM + j];
        float wm = a;
        #pragma unroll
        for (int o = 16; o; o >>= 1) wm = fmaxf(wm, __shfl_xor_sync(0xffffffffu, wm, o));
        if (lane == 0) wred[wid] = wm;
    }
    __syncthreads();
    m = fmaxf(fmaxf(wred[0], wred[1]), fmaxf(wred[2], wred[3]));
    if (h == 0) {
        p[j] = __expf(a - m);
        if (len > 1) e_cur = emit[BN + b * N_DIM + j];   // prefetch emit[1]
    }
    __syncthreads();

    // ---- recurrence ----
    for (int t = 1; t < len; t++) {
        // prefetch next step's emissions (overlaps the GEMV below)
        float e_nxt = 0.f;
        if (h == 0 && t + 1 < len)
            e_nxt = emit[(t + 1) * BN + b * N_DIM + j];

        // partial_j = sum over my 64 i's of p_i * E[i][j]
        const float4* p4 = reinterpret_cast<const float4*>(p) + h * 16;
        float partial = 0.f;
        #pragma unroll
        for (int k = 0; k < 16; k++) {
            float4 v = p4[k];
            partial = fmaf(v.x, E[4 * k + 0], partial);
            partial = fmaf(v.y, E[4 * k + 1], partial);
            partial = fmaf(v.z, E[4 * k + 2], partial);
            partial = fmaf(v.w, E[4 * k + 3], partial);
        }
        if (h == 1) psum[j] = partial;
        __syncthreads();

        if (h == 0) {
            float s = partial + psum[j];
            a = m + __logf(s) + e_cur;
            float wm = a;
            #pragma unroll
            for (int o = 16; o; o >>= 1) wm = fmaxf(wm, __shfl_xor_sync(0xffffffffu, wm, o));
            if (lane == 0) wred[wid] = wm;
        }
        __syncthreads();

        m = fmaxf(fmaxf(wred[0], wred[1]), fmaxf(wred[2], wred[3]));
        if (h == 0) p[j] = __expf(a - m);
        e_cur = e_nxt;
        __syncthreads();
    }

    // ---- finalize: logZ_b = lse_j(alpha_j + etrans_j) ----
    float v  = (h == 0) ? (a + etrans[j]) : -3.4e38f;
    float wm = v;
    #pragma unroll
    for (int o = 16; o; o >>= 1) wm = fmaxf(wm, __shfl_xor_sync(0xffffffffu, wm, o));
    if (lane == 0) wred[wid] = wm;
    __syncthreads();
    float m2 = wred[0];
    #pragma unroll
    for (int i = 1; i < 8; i++) m2 = fmaxf(m2, wred[i]);

    float ev = (h == 0) ? __expf(v - m2) : 0.f;
    #pragma unroll
    for (int o = 16; o; o >>= 1) ev += __shfl_xor_sync(0xffffffffu, ev, o);
    if (lane == 0) psum[wid] = ev;
    __syncthreads();
    if (tid == 0) {
        float ssum = 0.f;
        #pragma unroll
        for (int i = 0; i < 8; i++) ssum += psum[i];
        g_logZ[b] = m2 + __logf(ssum);
    }
}

// ---------------------------------------------------------------------------
// Kernel C: deterministic double-precision reduction -> (logZ - score) / B
// ---------------------------------------------------------------------------
__global__ void reduce_kernel(float* __restrict__ out) {
    __shared__ double sh[B_DIM];
    int tid = threadIdx.x;
    sh[tid] = (double)g_logZ[tid] - (double)g_score[tid];
    __syncthreads();
    for (int o = B_DIM / 2; o; o >>= 1) {
        if (tid < o) sh[tid] += sh[tid + o];
        __syncthreads();
    }
    if (tid == 0) out[0] = (float)(sh[0] / (double)B_DIM);
}

extern "C" void kernel_launch(void* const* d_in, const int* in_sizes, int n_in,
                              void* d_out, int out_size) {
    const float* emit   = (const float*)d_in[0];
    const int*   target = (const int*)d_in[1];
    const int*   mask   = (const int*)d_in[2];
    const float* trans  = (const float*)d_in[3];
    const float* strans = (const float*)d_in[4];
    const float* etrans = (const float*)d_in[5];

    score_len_kernel<<<(B_DIM * 32 + 255) / 256, 256>>>(emit, target, mask,
                                                        trans, strans, etrans);
    forward_kernel<<<B_DIM, 256>>>(emit, trans, strans, etrans);
    reduce_kernel<<<1, B_DIM>>>((float*)d_out);
}